// round 14
// baseline (speedup 1.0000x reference)
#include <cuda_runtime.h>
#include <cuda_fp16.h>
#include <math.h>
#include <stdint.h>

#define BB 4096
#define TT 200
#define CC 16
#define HH 112
#define GG 448

#define NSTAT_BLK 256
#define STAT_THREADS 256

#define MB 32            // batch rows per CTA: two independent 16-row groups
#define TPB 256          // 8 warps, each owns 7 n-tiles for BOTH groups
#define NCTA (BB/MB)     // 128
#define KT_H 7           // k16-tiles for h (112)
#define GBUF (KT_H * 128)       // words per (group,parity) A buffer (896)

// ---------------- device scratch ----------------
__device__ float g_part[NSTAT_BLK * 32];
__device__ uint2 g_Wfrag_h[56 * KT_H * 32];   // 100,352 B
__device__ uint2 g_Wfrag_x[56 * 32];          // 14,336 B (BN-folded)
__device__ float g_bias_n[GG];                // bias per col n (n = j*4 + gate)

// ---------------- helpers ----------------
static __device__ __forceinline__ uint32_t pkh(float lo, float hi) {
    uint32_t r; asm("cvt.rn.f16x2.f32 %0, %1, %2;" : "=r"(r) : "f"(hi), "f"(lo)); return r;
}
static __device__ __forceinline__ void hmma16(float* c, const uint4 a, const uint2 b) {
    asm volatile("mma.sync.aligned.m16n8k16.row.col.f32.f16.f16.f32 "
                 "{%0,%1,%2,%3}, {%4,%5,%6,%7}, {%8,%9}, {%0,%1,%2,%3};"
                 : "+f"(c[0]), "+f"(c[1]), "+f"(c[2]), "+f"(c[3])
                 : "r"(a.x), "r"(a.y), "r"(a.z), "r"(a.w), "r"(b.x), "r"(b.y));
}
static __device__ __forceinline__ float tanha(float z) {
    float r; asm("tanh.approx.f32 %0, %1;" : "=f"(r) : "f"(z)); return r;
}
static __device__ __forceinline__ float siga(float z) {
    return fmaf(tanha(z * 0.5f), 0.5f, 0.5f);
}
static __device__ __forceinline__ float sigf(float z) {
    return __fdividef(1.f, 1.f + __expf(-z));
}
static __device__ __forceinline__ float tanhf2(float z) {
    return 2.f * sigf(2.f * z) - 1.f;
}

// ---------------- kernel 1: per-channel sum / sumsq (deterministic) --------
__global__ void k_stats(const float* __restrict__ x) {
    const int tid = threadIdx.x, bid = blockIdx.x;
    const float4* x4 = (const float4*)x;
    const int n4 = BB * TT * CC / 4;
    float4 s = make_float4(0.f, 0.f, 0.f, 0.f);
    float4 q = make_float4(0.f, 0.f, 0.f, 0.f);
    for (int i = bid * STAT_THREADS + tid; i < n4; i += NSTAT_BLK * STAT_THREADS) {
        float4 v = x4[i];
        s.x += v.x; s.y += v.y; s.z += v.z; s.w += v.w;
        q.x += v.x * v.x; q.y += v.y * v.y; q.z += v.z * v.z; q.w += v.w * v.w;
    }
    __shared__ float sm[STAT_THREADS][8];
    sm[tid][0] = s.x; sm[tid][1] = s.y; sm[tid][2] = s.z; sm[tid][3] = s.w;
    sm[tid][4] = q.x; sm[tid][5] = q.y; sm[tid][6] = q.z; sm[tid][7] = q.w;
    __syncthreads();
    for (int st = STAT_THREADS / 2; st >= 4; st >>= 1) {
        if (tid < st) {
#pragma unroll
            for (int w = 0; w < 8; w++) sm[tid][w] += sm[tid + st][w];
        }
        __syncthreads();
    }
    if (tid < 4) {
#pragma unroll
        for (int w = 0; w < 8; w++) g_part[bid * 32 + tid * 8 + w] = sm[tid][w];
    }
}

// ---------------- kernel 2: finalize stats, fold BN, build fp16 frags ------
__global__ void k_prep(const float* __restrict__ gamma, const float* __restrict__ beta,
                       const float* __restrict__ W_ih, const float* __restrict__ W_hh,
                       const float* __restrict__ b_ih, const float* __restrict__ b_hh) {
    __shared__ float red[32];
    __shared__ float scale[CC], shift[CC];
    const int tid = threadIdx.x;
    if (tid < 32) {
        float a = 0.f;
        for (int b = 0; b < NSTAT_BLK; b++) a += g_part[b * 32 + tid];
        red[tid] = a;
    }
    __syncthreads();
    if (tid < CC) {
        const int cg = tid >> 2, qq = tid & 3;
        const float n = (float)(BB * TT);
        const float sum = red[cg * 8 + qq];
        const float ssq = red[cg * 8 + 4 + qq];
        const float mean = sum / n;
        const float var = ssq / n - mean * mean;
        const float sc = gamma[tid] * rsqrtf(var + 1e-5f);
        scale[tid] = sc;
        shift[tid] = beta[tid] - mean * sc;
    }
    __syncthreads();

    for (int n = tid; n < GG; n += blockDim.x) {
        const int grow = (n & 3) * HH + (n >> 2);
        float bsum = b_ih[grow] + b_hh[grow];
#pragma unroll
        for (int c = 0; c < CC; c++) bsum += W_ih[grow * CC + c] * shift[c];
        g_bias_n[n] = bsum;
    }

    for (int idx = tid; idx < 56 * KT_H * 32; idx += blockDim.x) {
        const int nt = idx / (KT_H * 32);
        const int kt = (idx / 32) % KT_H;
        const int l = idx & 31;
        const int n = nt * 8 + (l >> 2);
        const int grow = (n & 3) * HH + (n >> 2);
        const int k0 = kt * 16 + 2 * (l & 3);
        g_Wfrag_h[idx] = make_uint2(
            pkh(W_hh[grow * HH + k0], W_hh[grow * HH + k0 + 1]),
            pkh(W_hh[grow * HH + k0 + 8], W_hh[grow * HH + k0 + 9]));
    }
    for (int idx = tid; idx < 56 * 32; idx += blockDim.x) {
        const int nt = idx / 32;
        const int l = idx & 31;
        const int n = nt * 8 + (l >> 2);
        const int grow = (n & 3) * HH + (n >> 2);
        const int k0 = 2 * (l & 3);
        g_Wfrag_x[idx] = make_uint2(
            pkh(W_ih[grow * CC + k0] * scale[k0], W_ih[grow * CC + k0 + 1] * scale[k0 + 1]),
            pkh(W_ih[grow * CC + k0 + 8] * scale[k0 + 8],
                W_ih[grow * CC + k0 + 9] * scale[k0 + 9]));
    }
}

// ---- epilogue for one n-tile of one group (expands at call site) ----------
#define EPI_TILE(CE, CCE, HLE, I, AWE, LAST) do {                              \
    const float s0 = evenq ? CE[I][2] : CE[I][0];                              \
    const float s1 = evenq ? CE[I][3] : CE[I][1];                              \
    const float r0 = __shfl_xor_sync(0xFFFFFFFF, s0, 1);                       \
    const float r1 = __shfl_xor_sync(0xFFFFFFFF, s1, 1);                       \
    const float zi = evenq ? CE[I][0] : r0;                                    \
    const float zf = evenq ? CE[I][1] : r1;                                    \
    const float zg = evenq ? r0 : CE[I][2];                                    \
    const float zo = evenq ? r1 : CE[I][3];                                    \
    const float ig = siga(zi);                                                 \
    const float fg = siga(zf);                                                 \
    const float gg = tanha(zg);                                                \
    const float og = siga(zo);                                                 \
    const float cn = fg * CCE[I] + ig * gg;                                    \
    CCE[I] = cn;                                                               \
    const float h = og * tanha(cn);                                            \
    if (LAST) {                                                                \
        HLE[I] = h;                                                            \
    } else {                                                                   \
        const float ho = __shfl_xor_sync(0xFFFFFFFF, h, 2);                    \
        if (q < 2) {                                                           \
            const uint32_t hw = pkh(h, ho);                                    \
            const int ntg = wn * 7 + I;                                        \
            const int ktv = ntg >> 3;                                          \
            const int c8 = ntg & 7;                                            \
            const int lane_r = rr * 4 + (c8 & 3);                              \
            const int e = q + 2 * (c8 >> 2);                                   \
            AWE[ktv * 128 + lane_r * 4 + e] = hw;                              \
        }                                                                      \
    }                                                                          \
} while (0)

// ---- seed + x-MMA for group (expands at call site) ------------------------
#define SEED_XMMA(CG, XL0, XH0, XL1, XH1) do {                                 \
    _Pragma("unroll")                                                          \
    for (int i = 0; i < 7; i++) {                                              \
        CG[i][0] = bias0[i]; CG[i][1] = bias1[i];                              \
        CG[i][2] = bias0[i]; CG[i][3] = bias1[i];                              \
    }                                                                          \
    uint4 ax;                                                                  \
    ax.x = pkh(XL0.x, XL0.y);                                                  \
    ax.y = pkh(XL1.x, XL1.y);                                                  \
    ax.z = pkh(XH0.x, XH0.y);                                                  \
    ax.w = pkh(XH1.x, XH1.y);                                                  \
    _Pragma("unroll")                                                          \
    for (int i = 0; i < 7; i++) hmma16(CG[i], ax, bx[i]);                      \
} while (0)

// ---- x prefetch for a group ------------------------------------------------
#define XFETCH(XR0, XR1, TNEXT, XL0, XH0, XL1, XH1) do {                       \
    const float2* p0 = (const float2*)&x[XR0 + (TNEXT) * CC + 2 * q];          \
    const float2* p1 = (const float2*)&x[XR1 + (TNEXT) * CC + 2 * q];          \
    XL0 = __ldg(p0); XH0 = __ldg(p0 + 4);                                      \
    XL1 = __ldg(p1); XH1 = __ldg(p1 + 4);                                      \
} while (0)

// ---------------- kernel 3: dual-stream persistent fp16 TC LSTM ------------
// Each warp carries TWO independent 16-row recurrence streams offset by half a
// step. Every phase = MMA(stream g) interleaved at kt-granularity with the
// OTHER stream's epilogue, so MUFU chains hide under MMA issue within one warp.
__global__ void __launch_bounds__(TPB, 1)
k_lstm(const float* __restrict__ x, const float* __restrict__ W_fc,
       const float* __restrict__ b_fc, float* __restrict__ out) {
    extern __shared__ __align__(16) char smem[];
    uint2* WfragS = (uint2*)smem;                           // 56*7*32 uint2
    uint32_t* AfragS = (uint32_t*)(smem + 56 * KT_H * 256); // [group][parity][896]
    float* Pfc = (float*)AfragS;                            // reused for FC partials

    const int tid = threadIdx.x;
    const int wn = tid >> 5;
    const int lane = tid & 31;
    const int q = lane & 3;
    const int rr = lane >> 2;
    const int b0 = blockIdx.x * MB;

    {
        const uint4* src = (const uint4*)g_Wfrag_h;
        uint4* dst = (uint4*)WfragS;
        for (int i = tid; i < 56 * KT_H * 16; i += TPB) dst[i] = src[i];
    }
    // zero parity-0 buffers of both groups (h(0) = 0)
    for (int i = tid; i < GBUF; i += TPB) {
        AfragS[0 * 2 * GBUF + i] = 0u;
        AfragS[1 * 2 * GBUF + i] = 0u;
    }

    uint2 bx[7];
#pragma unroll
    for (int i = 0; i < 7; i++) bx[i] = g_Wfrag_x[(wn * 7 + i) * 32 + lane];

    float bias0[7], bias1[7];
#pragma unroll
    for (int i = 0; i < 7; i++) {
        const int n = (wn * 7 + i) * 8 + 2 * q;
        bias0[i] = g_bias_n[n];
        bias1[i] = g_bias_n[n + 1];
    }

    // group row bases: G0 = rows 0-15, G1 = rows 16-31
    const size_t x0r0 = (size_t)(b0 + rr) * (TT * CC);
    const size_t x0r1 = (size_t)(b0 + rr + 8) * (TT * CC);
    const size_t x1r0 = (size_t)(b0 + 16 + rr) * (TT * CC);
    const size_t x1r1 = (size_t)(b0 + 16 + rr + 8) * (TT * CC);
    float2 x0l0, x0h0, x0l1, x0h1, x1l0, x1h0, x1l1, x1h1;
    XFETCH(x0r0, x0r1, 0, x0l0, x0h0, x0l1, x0h1);
    XFETCH(x1r0, x1r1, 0, x1l0, x1h0, x1l1, x1h1);

    float c0[7][4], c1[7][4];
    float cc0[7], cc1[7], hl0[7], hl1[7];
#pragma unroll
    for (int i = 0; i < 7; i++) { cc0[i] = 0.f; cc1[i] = 0.f; }
    const bool evenq = (q & 1) == 0;

    __syncthreads();   // staging + zero buffers visible

    // ---- prologue: MMA(G0, t=0) (h-part reads zero buffer -> contributes 0)
    SEED_XMMA(c0, x0l0, x0h0, x0l1, x0h1);
    {
        const uint32_t* Ar = AfragS;   // G0 parity 0
#pragma unroll
        for (int kt = 0; kt < KT_H; kt++) {
            const uint4 a = *(const uint4*)&Ar[kt * 128 + lane * 4];
#pragma unroll
            for (int i = 0; i < 7; i++)
                hmma16(c0[i], a, WfragS[((wn * 7 + i) * KT_H + kt) * 32 + lane]);
        }
    }
    XFETCH(x0r0, x0r1, 1, x0l0, x0h0, x0l1, x0h1);

    for (int t = 0; t < TT - 1; t++) {
        // ===== phase A: MMA(G1, t) + epilogue(G0, t) =====
        __syncthreads();
        {
            SEED_XMMA(c1, x1l0, x1h0, x1l1, x1h1);
            const uint32_t* Ar = AfragS + 2 * GBUF + (t & 1) * GBUF;
            uint32_t* Aw0 = AfragS + ((t + 1) & 1) * GBUF;   // G0 write buffer
#pragma unroll
            for (int kt = 0; kt < KT_H; kt++) {
                const uint4 a = *(const uint4*)&Ar[kt * 128 + lane * 4];
#pragma unroll
                for (int i = 0; i < 7; i++)
                    hmma16(c1[i], a, WfragS[((wn * 7 + i) * KT_H + kt) * 32 + lane]);
                EPI_TILE(c0, cc0, hl0, kt, Aw0, false);
            }
            XFETCH(x1r0, x1r1, t + 1, x1l0, x1h0, x1l1, x1h1);
        }
        // ===== phase B: MMA(G0, t+1) + epilogue(G1, t) =====
        __syncthreads();
        {
            SEED_XMMA(c0, x0l0, x0h0, x0l1, x0h1);
            const uint32_t* Ar = AfragS + ((t + 1) & 1) * GBUF;
            uint32_t* Aw1 = AfragS + 2 * GBUF + ((t + 1) & 1) * GBUF;  // G1 write
#pragma unroll
            for (int kt = 0; kt < KT_H; kt++) {
                const uint4 a = *(const uint4*)&Ar[kt * 128 + lane * 4];
#pragma unroll
                for (int i = 0; i < 7; i++)
                    hmma16(c0[i], a, WfragS[((wn * 7 + i) * KT_H + kt) * 32 + lane]);
                EPI_TILE(c1, cc1, hl1, kt, Aw1, false);
            }
            if (t + 2 < TT) XFETCH(x0r0, x0r1, t + 2, x0l0, x0h0, x0l1, x0h1);
        }
    }

    // ---- tail: t = TT-1 ----
    __syncthreads();
    {   // phase A: MMA(G1, TT-1) + epilogue(G0, TT-1) -> hlast0
        SEED_XMMA(c1, x1l0, x1h0, x1l1, x1h1);
        const uint32_t* Ar = AfragS + 2 * GBUF + ((TT - 1) & 1) * GBUF;
        uint32_t* Awd = AfragS + (TT & 1) * GBUF;   // dummy (unused after)
#pragma unroll
        for (int kt = 0; kt < KT_H; kt++) {
            const uint4 a = *(const uint4*)&Ar[kt * 128 + lane * 4];
#pragma unroll
            for (int i = 0; i < 7; i++)
                hmma16(c1[i], a, WfragS[((wn * 7 + i) * KT_H + kt) * 32 + lane]);
            EPI_TILE(c0, cc0, hl0, kt, Awd, true);
        }
    }
    {   // epilogue(G1, TT-1) -> hlast1
        uint32_t* Awd = AfragS + 2 * GBUF + (TT & 1) * GBUF;
#pragma unroll
        for (int i = 0; i < 7; i++) EPI_TILE(c1, cc1, hl1, i, Awd, true);
    }

    // ---- final FC (accurate tanh on output)
    __syncthreads();   // Pfc aliases AfragS
    float p0[6], p1[6];
#pragma unroll
    for (int o = 0; o < 6; o++) { p0[o] = 0.f; p1[o] = 0.f; }
#pragma unroll
    for (int i = 0; i < 7; i++) {
        const int j = 2 * (wn * 7 + i) + (q >> 1);
#pragma unroll
        for (int o = 0; o < 6; o++) {
            const float wv = __ldg(&W_fc[o * HH + j]);
            p0[o] += hl0[i] * wv;
            p1[o] += hl1[i] * wv;
        }
    }
#pragma unroll
    for (int o = 0; o < 6; o++) {
        p0[o] += __shfl_xor_sync(0xFFFFFFFF, p0[o], 2);
        p1[o] += __shfl_xor_sync(0xFFFFFFFF, p1[o], 2);
    }
    if ((lane & 2) == 0) {
        const int row0 = rr + (evenq ? 0 : 8);
#pragma unroll
        for (int o = 0; o < 6; o++) {
            Pfc[(wn * MB + row0) * 6 + o] = p0[o];
            Pfc[(wn * MB + 16 + row0) * 6 + o] = p1[o];
        }
    }
    __syncthreads();
    if (tid < MB * 6) {
        const int row = tid / 6, o = tid % 6;
        float s = b_fc[o];
#pragma unroll
        for (int w2 = 0; w2 < 8; w2++) s += Pfc[(w2 * MB + row) * 6 + o];
        out[(size_t)(b0 + row) * 6 + o] = tanhf2(s);
    }
}

// ---------------- launch ----------------------------------------------------
extern "C" void kernel_launch(void* const* d_in, const int* in_sizes, int n_in,
                              void* d_out, int out_size) {
    const float* x     = (const float*)d_in[0];
    const float* gamma = (const float*)d_in[1];
    const float* beta  = (const float*)d_in[2];
    const float* W_ih  = (const float*)d_in[3];
    const float* W_hh  = (const float*)d_in[4];
    const float* b_ih  = (const float*)d_in[5];
    const float* b_hh  = (const float*)d_in[6];
    const float* W_fc  = (const float*)d_in[7];
    const float* b_fc  = (const float*)d_in[8];
    float* out = (float*)d_out;

    const int smem_bytes = 56 * KT_H * 256 + 4 * GBUF * 4;  // 100352 + 14336 = 114688
    cudaFuncSetAttribute(k_lstm, cudaFuncAttributeMaxDynamicSharedMemorySize, smem_bytes);

    k_stats<<<NSTAT_BLK, STAT_THREADS>>>(x);
    k_prep<<<1, 512>>>(gamma, beta, W_ih, W_hh, b_ih, b_hh);
    k_lstm<<<NCTA, TPB, smem_bytes>>>(x, W_fc, b_fc, out);
}

// round 15
// speedup vs baseline: 1.0045x; 1.0045x over previous
#include <cuda_runtime.h>
#include <cuda_fp16.h>
#include <math.h>
#include <stdint.h>

#define BB 4096
#define TT 200
#define CC 16
#define HH 112
#define GG 448

#define NSTAT_BLK 256
#define STAT_THREADS 256

#define MB 32            // batch rows per CTA: two independent 16-row groups
#define TPB 256          // 8 warps, each owns 7 n-tiles for BOTH groups
#define NCTA (BB/MB)     // 128
#define KT_H 7           // k16-tiles for h (112)
#define GBUF (KT_H * 128)       // words per (group,parity) A buffer (896)

// ---------------- device scratch ----------------
__device__ float g_part[NSTAT_BLK * 32];
__device__ uint2 g_Wfrag_h[56 * KT_H * 32];   // 100,352 B
__device__ uint2 g_Wfrag_x[56 * 32];          // 14,336 B (BN-folded)
__device__ float g_bias_n[GG];                // bias per col n (n = j*4 + gate)

// ---------------- helpers ----------------
static __device__ __forceinline__ uint32_t pkh(float lo, float hi) {
    uint32_t r; asm("cvt.rn.f16x2.f32 %0, %1, %2;" : "=r"(r) : "f"(hi), "f"(lo)); return r;
}
static __device__ __forceinline__ void hmma16(float* c, const uint4 a, const uint2 b) {
    asm volatile("mma.sync.aligned.m16n8k16.row.col.f32.f16.f16.f32 "
                 "{%0,%1,%2,%3}, {%4,%5,%6,%7}, {%8,%9}, {%0,%1,%2,%3};"
                 : "+f"(c[0]), "+f"(c[1]), "+f"(c[2]), "+f"(c[3])
                 : "r"(a.x), "r"(a.y), "r"(a.z), "r"(a.w), "r"(b.x), "r"(b.y));
}
static __device__ __forceinline__ float tanha(float z) {
    float r; asm("tanh.approx.f32 %0, %1;" : "=f"(r) : "f"(z)); return r;
}
static __device__ __forceinline__ float siga(float z) {
    return fmaf(tanha(z * 0.5f), 0.5f, 0.5f);
}
static __device__ __forceinline__ float sigf(float z) {
    return __fdividef(1.f, 1.f + __expf(-z));
}
static __device__ __forceinline__ float tanhf2(float z) {
    return 2.f * sigf(2.f * z) - 1.f;
}

// ---------------- kernel 1: per-channel sum / sumsq (deterministic) --------
__global__ void k_stats(const float* __restrict__ x) {
    const int tid = threadIdx.x, bid = blockIdx.x;
    const float4* x4 = (const float4*)x;
    const int n4 = BB * TT * CC / 4;
    float4 s = make_float4(0.f, 0.f, 0.f, 0.f);
    float4 q = make_float4(0.f, 0.f, 0.f, 0.f);
    for (int i = bid * STAT_THREADS + tid; i < n4; i += NSTAT_BLK * STAT_THREADS) {
        float4 v = x4[i];
        s.x += v.x; s.y += v.y; s.z += v.z; s.w += v.w;
        q.x += v.x * v.x; q.y += v.y * v.y; q.z += v.z * v.z; q.w += v.w * v.w;
    }
    __shared__ float sm[STAT_THREADS][8];
    sm[tid][0] = s.x; sm[tid][1] = s.y; sm[tid][2] = s.z; sm[tid][3] = s.w;
    sm[tid][4] = q.x; sm[tid][5] = q.y; sm[tid][6] = q.z; sm[tid][7] = q.w;
    __syncthreads();
    for (int st = STAT_THREADS / 2; st >= 4; st >>= 1) {
        if (tid < st) {
#pragma unroll
            for (int w = 0; w < 8; w++) sm[tid][w] += sm[tid + st][w];
        }
        __syncthreads();
    }
    if (tid < 4) {
#pragma unroll
        for (int w = 0; w < 8; w++) g_part[bid * 32 + tid * 8 + w] = sm[tid][w];
    }
}

// ---------------- kernel 2: finalize stats, fold BN, build fp16 frags ------
__global__ void k_prep(const float* __restrict__ gamma, const float* __restrict__ beta,
                       const float* __restrict__ W_ih, const float* __restrict__ W_hh,
                       const float* __restrict__ b_ih, const float* __restrict__ b_hh) {
    __shared__ float red[32];
    __shared__ float scale[CC], shift[CC];
    const int tid = threadIdx.x;
    if (tid < 32) {
        float a = 0.f;
        for (int b = 0; b < NSTAT_BLK; b++) a += g_part[b * 32 + tid];
        red[tid] = a;
    }
    __syncthreads();
    if (tid < CC) {
        const int cg = tid >> 2, qq = tid & 3;
        const float n = (float)(BB * TT);
        const float sum = red[cg * 8 + qq];
        const float ssq = red[cg * 8 + 4 + qq];
        const float mean = sum / n;
        const float var = ssq / n - mean * mean;
        const float sc = gamma[tid] * rsqrtf(var + 1e-5f);
        scale[tid] = sc;
        shift[tid] = beta[tid] - mean * sc;
    }
    __syncthreads();

    for (int n = tid; n < GG; n += blockDim.x) {
        const int grow = (n & 3) * HH + (n >> 2);
        float bsum = b_ih[grow] + b_hh[grow];
#pragma unroll
        for (int c = 0; c < CC; c++) bsum += W_ih[grow * CC + c] * shift[c];
        g_bias_n[n] = bsum;
    }

    for (int idx = tid; idx < 56 * KT_H * 32; idx += blockDim.x) {
        const int nt = idx / (KT_H * 32);
        const int kt = (idx / 32) % KT_H;
        const int l = idx & 31;
        const int n = nt * 8 + (l >> 2);
        const int grow = (n & 3) * HH + (n >> 2);
        const int k0 = kt * 16 + 2 * (l & 3);
        g_Wfrag_h[idx] = make_uint2(
            pkh(W_hh[grow * HH + k0], W_hh[grow * HH + k0 + 1]),
            pkh(W_hh[grow * HH + k0 + 8], W_hh[grow * HH + k0 + 9]));
    }
    for (int idx = tid; idx < 56 * 32; idx += blockDim.x) {
        const int nt = idx / 32;
        const int l = idx & 31;
        const int n = nt * 8 + (l >> 2);
        const int grow = (n & 3) * HH + (n >> 2);
        const int k0 = 2 * (l & 3);
        g_Wfrag_x[idx] = make_uint2(
            pkh(W_ih[grow * CC + k0] * scale[k0], W_ih[grow * CC + k0 + 1] * scale[k0 + 1]),
            pkh(W_ih[grow * CC + k0 + 8] * scale[k0 + 8],
                W_ih[grow * CC + k0 + 9] * scale[k0 + 9]));
    }
}

// ---- epilogue for one n-tile of one group (expands at call site) ----------
#define EPI_TILE(CE, CCE, HLE, I, AWE, LAST) do {                              \
    const float s0 = evenq ? CE[I][2] : CE[I][0];                              \
    const float s1 = evenq ? CE[I][3] : CE[I][1];                              \
    const float r0 = __shfl_xor_sync(0xFFFFFFFF, s0, 1);                       \
    const float r1 = __shfl_xor_sync(0xFFFFFFFF, s1, 1);                       \
    const float zi = evenq ? CE[I][0] : r0;                                    \
    const float zf = evenq ? CE[I][1] : r1;                                    \
    const float zg = evenq ? r0 : CE[I][2];                                    \
    const float zo = evenq ? r1 : CE[I][3];                                    \
    const float ig = siga(zi);                                                 \
    const float fg = siga(zf);                                                 \
    const float gg = tanha(zg);                                                \
    const float og = siga(zo);                                                 \
    const float cn = fg * CCE[I] + ig * gg;                                    \
    CCE[I] = cn;                                                               \
    const float h = og * tanha(cn);                                            \
    if (LAST) {                                                                \
        HLE[I] = h;                                                            \
    } else {                                                                   \
        const float ho = __shfl_xor_sync(0xFFFFFFFF, h, 2);                    \
        if (q < 2) {                                                           \
            const uint32_t hw = pkh(h, ho);                                    \
            const int ntg = wn * 7 + I;                                        \
            const int ktv = ntg >> 3;                                          \
            const int c8 = ntg & 7;                                            \
            const int lane_r = rr * 4 + (c8 & 3);                              \
            const int e = q + 2 * (c8 >> 2);                                   \
            AWE[ktv * 128 + lane_r * 4 + e] = hw;                              \
        }                                                                      \
    }                                                                          \
} while (0)

// ---- seed + x-MMA for group (expands at call site) ------------------------
#define SEED_XMMA(CG, XL0, XH0, XL1, XH1) do {                                 \
    _Pragma("unroll")                                                          \
    for (int i = 0; i < 7; i++) {                                              \
        CG[i][0] = bias0[i]; CG[i][1] = bias1[i];                              \
        CG[i][2] = bias0[i]; CG[i][3] = bias1[i];                              \
    }                                                                          \
    uint4 ax;                                                                  \
    ax.x = pkh(XL0.x, XL0.y);                                                  \
    ax.y = pkh(XL1.x, XL1.y);                                                  \
    ax.z = pkh(XH0.x, XH0.y);                                                  \
    ax.w = pkh(XH1.x, XH1.y);                                                  \
    _Pragma("unroll")                                                          \
    for (int i = 0; i < 7; i++) hmma16(CG[i], ax, bx[i]);                      \
} while (0)

// ---- x prefetch for a group ------------------------------------------------
#define XFETCH(XR0, XR1, TNEXT, XL0, XH0, XL1, XH1) do {                       \
    const float2* p0 = (const float2*)&x[XR0 + (TNEXT) * CC + 2 * q];          \
    const float2* p1 = (const float2*)&x[XR1 + (TNEXT) * CC + 2 * q];          \
    XL0 = __ldg(p0); XH0 = __ldg(p0 + 4);                                      \
    XL1 = __ldg(p1); XH1 = __ldg(p1 + 4);                                      \
} while (0)

// ---------------- kernel 3: dual-stream persistent fp16 TC LSTM ------------
// Each warp carries TWO independent 16-row recurrence streams offset by half a
// step. Every phase = MMA(stream g) interleaved at kt-granularity with the
// OTHER stream's epilogue, so MUFU chains hide under MMA issue within one warp.
__global__ void __launch_bounds__(TPB, 1)
k_lstm(const float* __restrict__ x, const float* __restrict__ W_fc,
       const float* __restrict__ b_fc, float* __restrict__ out) {
    extern __shared__ __align__(16) char smem[];
    uint2* WfragS = (uint2*)smem;                           // 56*7*32 uint2
    uint32_t* AfragS = (uint32_t*)(smem + 56 * KT_H * 256); // [group][parity][896]
    float* Pfc = (float*)AfragS;                            // reused for FC partials

    const int tid = threadIdx.x;
    const int wn = tid >> 5;
    const int lane = tid & 31;
    const int q = lane & 3;
    const int rr = lane >> 2;
    const int b0 = blockIdx.x * MB;

    {
        const uint4* src = (const uint4*)g_Wfrag_h;
        uint4* dst = (uint4*)WfragS;
        for (int i = tid; i < 56 * KT_H * 16; i += TPB) dst[i] = src[i];
    }
    // zero parity-0 buffers of both groups (h(0) = 0)
    for (int i = tid; i < GBUF; i += TPB) {
        AfragS[0 * 2 * GBUF + i] = 0u;
        AfragS[1 * 2 * GBUF + i] = 0u;
    }

    uint2 bx[7];
#pragma unroll
    for (int i = 0; i < 7; i++) bx[i] = g_Wfrag_x[(wn * 7 + i) * 32 + lane];

    float bias0[7], bias1[7];
#pragma unroll
    for (int i = 0; i < 7; i++) {
        const int n = (wn * 7 + i) * 8 + 2 * q;
        bias0[i] = g_bias_n[n];
        bias1[i] = g_bias_n[n + 1];
    }

    // group row bases: G0 = rows 0-15, G1 = rows 16-31
    const size_t x0r0 = (size_t)(b0 + rr) * (TT * CC);
    const size_t x0r1 = (size_t)(b0 + rr + 8) * (TT * CC);
    const size_t x1r0 = (size_t)(b0 + 16 + rr) * (TT * CC);
    const size_t x1r1 = (size_t)(b0 + 16 + rr + 8) * (TT * CC);
    float2 x0l0, x0h0, x0l1, x0h1, x1l0, x1h0, x1l1, x1h1;
    XFETCH(x0r0, x0r1, 0, x0l0, x0h0, x0l1, x0h1);
    XFETCH(x1r0, x1r1, 0, x1l0, x1h0, x1l1, x1h1);

    float c0[7][4], c1[7][4];
    float cc0[7], cc1[7], hl0[7], hl1[7];
#pragma unroll
    for (int i = 0; i < 7; i++) { cc0[i] = 0.f; cc1[i] = 0.f; }
    const bool evenq = (q & 1) == 0;

    __syncthreads();   // staging + zero buffers visible

    // ---- prologue: MMA(G0, t=0) (h-part reads zero buffer -> contributes 0)
    SEED_XMMA(c0, x0l0, x0h0, x0l1, x0h1);
    {
        const uint32_t* Ar = AfragS;   // G0 parity 0
#pragma unroll
        for (int kt = 0; kt < KT_H; kt++) {
            const uint4 a = *(const uint4*)&Ar[kt * 128 + lane * 4];
#pragma unroll
            for (int i = 0; i < 7; i++)
                hmma16(c0[i], a, WfragS[((wn * 7 + i) * KT_H + kt) * 32 + lane]);
        }
    }
    XFETCH(x0r0, x0r1, 1, x0l0, x0h0, x0l1, x0h1);

    for (int t = 0; t < TT - 1; t++) {
        // ===== phase A: MMA(G1, t) + epilogue(G0, t) =====
        __syncthreads();
        {
            SEED_XMMA(c1, x1l0, x1h0, x1l1, x1h1);
            const uint32_t* Ar = AfragS + 2 * GBUF + (t & 1) * GBUF;
            uint32_t* Aw0 = AfragS + ((t + 1) & 1) * GBUF;   // G0 write buffer
#pragma unroll
            for (int kt = 0; kt < KT_H; kt++) {
                const uint4 a = *(const uint4*)&Ar[kt * 128 + lane * 4];
#pragma unroll
                for (int i = 0; i < 7; i++)
                    hmma16(c1[i], a, WfragS[((wn * 7 + i) * KT_H + kt) * 32 + lane]);
                EPI_TILE(c0, cc0, hl0, kt, Aw0, false);
            }
            XFETCH(x1r0, x1r1, t + 1, x1l0, x1h0, x1l1, x1h1);
        }
        // ===== phase B: MMA(G0, t+1) + epilogue(G1, t) =====
        __syncthreads();
        {
            SEED_XMMA(c0, x0l0, x0h0, x0l1, x0h1);
            const uint32_t* Ar = AfragS + ((t + 1) & 1) * GBUF;
            uint32_t* Aw1 = AfragS + 2 * GBUF + ((t + 1) & 1) * GBUF;  // G1 write
#pragma unroll
            for (int kt = 0; kt < KT_H; kt++) {
                const uint4 a = *(const uint4*)&Ar[kt * 128 + lane * 4];
#pragma unroll
                for (int i = 0; i < 7; i++)
                    hmma16(c0[i], a, WfragS[((wn * 7 + i) * KT_H + kt) * 32 + lane]);
                EPI_TILE(c1, cc1, hl1, kt, Aw1, false);
            }
            if (t + 2 < TT) XFETCH(x0r0, x0r1, t + 2, x0l0, x0h0, x0l1, x0h1);
        }
    }

    // ---- tail: t = TT-1 ----
    __syncthreads();
    {   // phase A: MMA(G1, TT-1) + epilogue(G0, TT-1) -> hlast0
        SEED_XMMA(c1, x1l0, x1h0, x1l1, x1h1);
        const uint32_t* Ar = AfragS + 2 * GBUF + ((TT - 1) & 1) * GBUF;
        uint32_t* Awd = AfragS + (TT & 1) * GBUF;   // dummy (unused after)
#pragma unroll
        for (int kt = 0; kt < KT_H; kt++) {
            const uint4 a = *(const uint4*)&Ar[kt * 128 + lane * 4];
#pragma unroll
            for (int i = 0; i < 7; i++)
                hmma16(c1[i], a, WfragS[((wn * 7 + i) * KT_H + kt) * 32 + lane]);
            EPI_TILE(c0, cc0, hl0, kt, Awd, true);
        }
    }
    {   // epilogue(G1, TT-1) -> hlast1
        uint32_t* Awd = AfragS + 2 * GBUF + (TT & 1) * GBUF;
#pragma unroll
        for (int i = 0; i < 7; i++) EPI_TILE(c1, cc1, hl1, i, Awd, true);
    }

    // ---- final FC (accurate tanh on output)
    __syncthreads();   // Pfc aliases AfragS
    float p0[6], p1[6];
#pragma unroll
    for (int o = 0; o < 6; o++) { p0[o] = 0.f; p1[o] = 0.f; }
#pragma unroll
    for (int i = 0; i < 7; i++) {
        const int j = 2 * (wn * 7 + i) + (q >> 1);
#pragma unroll
        for (int o = 0; o < 6; o++) {
            const float wv = __ldg(&W_fc[o * HH + j]);
            p0[o] += hl0[i] * wv;
            p1[o] += hl1[i] * wv;
        }
    }
#pragma unroll
    for (int o = 0; o < 6; o++) {
        p0[o] += __shfl_xor_sync(0xFFFFFFFF, p0[o], 2);
        p1[o] += __shfl_xor_sync(0xFFFFFFFF, p1[o], 2);
    }
    if ((lane & 2) == 0) {
        const int row0 = rr + (evenq ? 0 : 8);
#pragma unroll
        for (int o = 0; o < 6; o++) {
            Pfc[(wn * MB + row0) * 6 + o] = p0[o];
            Pfc[(wn * MB + 16 + row0) * 6 + o] = p1[o];
        }
    }
    __syncthreads();
    if (tid < MB * 6) {
        const int row = tid / 6, o = tid % 6;
        float s = b_fc[o];
#pragma unroll
        for (int w2 = 0; w2 < 8; w2++) s += Pfc[(w2 * MB + row) * 6 + o];
        out[(size_t)(b0 + row) * 6 + o] = tanhf2(s);
    }
}

// ---------------- launch ----------------------------------------------------
extern "C" void kernel_launch(void* const* d_in, const int* in_sizes, int n_in,
                              void* d_out, int out_size) {
    const float* x     = (const float*)d_in[0];
    const float* gamma = (const float*)d_in[1];
    const float* beta  = (const float*)d_in[2];
    const float* W_ih  = (const float*)d_in[3];
    const float* W_hh  = (const float*)d_in[4];
    const float* b_ih  = (const float*)d_in[5];
    const float* b_hh  = (const float*)d_in[6];
    const float* W_fc  = (const float*)d_in[7];
    const float* b_fc  = (const float*)d_in[8];
    float* out = (float*)d_out;

    const int smem_bytes = 56 * KT_H * 256 + 4 * GBUF * 4;  // 100352 + 14336 = 114688
    cudaFuncSetAttribute(k_lstm, cudaFuncAttributeMaxDynamicSharedMemorySize, smem_bytes);

    k_stats<<<NSTAT_BLK, STAT_THREADS>>>(x);
    k_prep<<<1, 512>>>(gamma, beta, W_ih, W_hh, b_ih, b_hh);
    k_lstm<<<NCTA, TPB, smem_bytes>>>(x, W_fc, b_fc, out);
}